// round 15
// baseline (speedup 1.0000x reference)
#include <cuda_runtime.h>
#include <cuda_fp16.h>
#include <math.h>
#include <stdint.h>

constexpr int Bn  = 4;
constexpr int Sn  = 2048;
constexpr int Dm  = 1024;
constexpr int Hn  = 16;
constexpr int Dh  = 64;
constexpr int MTOT = Bn * Sn;   // 8192

// fp16 scratch
__device__ __half g_Q16[(size_t)MTOT * Dm];   // pre-scaled by 0.125*log2e
__device__ __half g_K16[(size_t)MTOT * Dm];
__device__ __half g_V16[(size_t)MTOT * Dm];
__device__ __half g_X16[(size_t)MTOT * Dm];
__device__ __half g_C16[(size_t)MTOT * Dm];
__device__ __half g_W16[4][(size_t)Dm * Dm];

// ---------------------------------------------------------------------------
// helpers
// ---------------------------------------------------------------------------
__device__ __forceinline__ float ex2(float x) {
    float y;
    asm("ex2.approx.ftz.f32 %0, %1;" : "=f"(y) : "f"(x));
    return y;
}

__device__ __forceinline__ void mma16h(float* d, const unsigned* a, const unsigned* b) {
    asm volatile(
        "mma.sync.aligned.m16n8k16.row.col.f32.f16.f16.f32 "
        "{%0,%1,%2,%3},{%4,%5,%6,%7},{%8,%9},{%0,%1,%2,%3};"
        : "+f"(d[0]), "+f"(d[1]), "+f"(d[2]), "+f"(d[3])
        : "r"(a[0]), "r"(a[1]), "r"(a[2]), "r"(a[3]), "r"(b[0]), "r"(b[1]));
}

__device__ __forceinline__ void ldm_x4(unsigned* r, uint32_t addr) {
    asm volatile(
        "ldmatrix.sync.aligned.m8n8.x4.shared.b16 {%0,%1,%2,%3}, [%4];"
        : "=r"(r[0]), "=r"(r[1]), "=r"(r[2]), "=r"(r[3]) : "r"(addr));
}

__device__ __forceinline__ unsigned packh2(float a, float b) {
    __half2 h = __floats2half2_rn(a, b);    // low = a
    return *reinterpret_cast<unsigned*>(&h);
}

__device__ __forceinline__ void cpasync16(uint32_t dst, const void* src) {
    asm volatile("cp.async.cg.shared.global [%0], [%1], 16;" :: "r"(dst), "l"(src));
}

// ---------------------------------------------------------------------------
// conversions
// ---------------------------------------------------------------------------
__global__ __launch_bounds__(256)
void k_cvtX(const float* __restrict__ src, __half* __restrict__ dst, int n4)
{
    int i = blockIdx.x * blockDim.x + threadIdx.x;
    if (i >= n4) return;
    float4 v = reinterpret_cast<const float4*>(src)[i];
    reinterpret_cast<__half2*>(dst)[i * 2 + 0] =
        __halves2half2(__float2half_rn(v.x), __float2half_rn(v.y));
    reinterpret_cast<__half2*>(dst)[i * 2 + 1] =
        __halves2half2(__float2half_rn(v.z), __float2half_rn(v.w));
}

__global__ __launch_bounds__(256)
void k_cvtW(const float* __restrict__ wq, const float* __restrict__ wk,
            const float* __restrict__ wv, const float* __restrict__ wo,
            __half* __restrict__ dst, int n4)
{
    int i = blockIdx.x * blockDim.x + threadIdx.x;
    if (i >= n4) return;
    const float* src = (blockIdx.y == 0) ? wq : (blockIdx.y == 1) ? wk
                       : (blockIdx.y == 2) ? wv : wo;
    __half* out = dst + (size_t)blockIdx.y * Dm * Dm;
    float4 v = reinterpret_cast<const float4*>(src)[i];
    reinterpret_cast<__half2*>(out)[i * 2 + 0] =
        __halves2half2(__float2half_rn(v.x), __float2half_rn(v.y));
    reinterpret_cast<__half2*>(out)[i * 2 + 1] =
        __halves2half2(__float2half_rn(v.z), __float2half_rn(v.w));
}

// ---------------------------------------------------------------------------
// Single-pass fp16 GEMM core: C = A . B^T + bias
// CTA tile 128x128, 4 warps (2x2) of 64x64, K-stage 64 (16 stages),
// cp.async double buffer. Stage tile: 128 rows x 144 B (128 data + 16 pad).
// mode: 0 = f32 out, 2 = fp16 out (scaled by oscale)
// ---------------------------------------------------------------------------
constexpr int GROWB = 144;
constexpr int GTILE = 128 * GROWB;           // 18432 B per matrix
constexpr int GEMM_SMEM = 2 * 2 * GTILE;     // 73728 B

__device__ __forceinline__ void gemm1_core(
    const __half* __restrict__ A,
    const __half* __restrict__ Bh,
    const float* __restrict__ bias,
    float* __restrict__ Cf, __half* __restrict__ Ch, int mode, float oscale)
{
    extern __shared__ __align__(16) unsigned char gsm[];

    const int tid  = threadIdx.x;
    const int lane = tid & 31;
    const int warp = tid >> 5;           // 0..3
    const int wm   = warp >> 1;          // 0..1
    const int wn   = warp & 1;           // 0..1
    const int m0   = blockIdx.y * 128;
    const int n0   = blockIdx.x * 128;

    const uint32_t smemBase = (uint32_t)__cvta_generic_to_shared(gsm);

    // fill: thread -> row tid, 8 x 16B chunks per matrix
    const uint32_t fDst = (uint32_t)(tid * GROWB);
    const __half* srcA = A  + (size_t)(m0 + tid) * Dm;
    const __half* srcB = Bh + (size_t)(n0 + tid) * Dm;

    // ldmatrix per-lane offsets (row stride 144 B)
    const uint32_t aOff = (uint32_t)((lane & 15) * GROWB + ((lane >> 4) & 1) * 16)
                          + wm * 64 * GROWB;
    const uint32_t bOff = (uint32_t)(((lane & 7) + ((lane >> 1) & 8)) * GROWB
                          + ((lane >> 3) & 1) * 16)
                          + wn * 64 * GROWB;

    float acc[4][8][4];
#pragma unroll
    for (int mf = 0; mf < 4; ++mf)
#pragma unroll
        for (int nf = 0; nf < 8; ++nf)
#pragma unroll
            for (int j = 0; j < 4; ++j) acc[mf][nf][j] = 0.f;

    const int NSTAGE = Dm / 64;   // 16

    // prologue: stage 0 -> buffer 0
    {
#pragma unroll
        for (int i = 0; i < 8; ++i) {
            cpasync16(smemBase + fDst + i * 16,         srcA + i * 8);
            cpasync16(smemBase + GTILE + fDst + i * 16, srcB + i * 8);
        }
        asm volatile("cp.async.commit_group;");
    }

    int buf = 0;
    for (int st = 0; st < NSTAGE; ++st) {
        asm volatile("cp.async.wait_group 0;");
        __syncthreads();

        if (st + 1 < NSTAGE) {
            const uint32_t nb = (uint32_t)((buf ^ 1) * 2 * GTILE);
#pragma unroll
            for (int i = 0; i < 8; ++i) {
                cpasync16(smemBase + nb + fDst + i * 16,
                          srcA + (st + 1) * 64 + i * 8);
                cpasync16(smemBase + nb + GTILE + fDst + i * 16,
                          srcB + (st + 1) * 64 + i * 8);
            }
            asm volatile("cp.async.commit_group;");
        }

        const uint32_t aB = smemBase + (uint32_t)(buf * 2 * GTILE) + aOff;
        const uint32_t bB = smemBase + (uint32_t)(buf * 2 * GTILE) + GTILE + bOff;

#pragma unroll
        for (int ks = 0; ks < 4; ++ks) {
            const uint32_t kadd = ks * 32;
            unsigned af[4][4], bf[8][2];
#pragma unroll
            for (int mf = 0; mf < 4; ++mf)
                ldm_x4(af[mf], aB + mf * (16 * GROWB) + kadd);
#pragma unroll
            for (int np = 0; np < 4; ++np) {
                unsigned t[4];
                ldm_x4(t, bB + np * (16 * GROWB) + kadd);
                bf[np * 2][0] = t[0]; bf[np * 2][1] = t[1];
                bf[np * 2 + 1][0] = t[2]; bf[np * 2 + 1][1] = t[3];
            }
#pragma unroll
            for (int mf = 0; mf < 4; ++mf)
#pragma unroll
                for (int nf = 0; nf < 8; ++nf)
                    mma16h(acc[mf][nf], af[mf], bf[nf]);
        }
        buf ^= 1;
    }

#pragma unroll
    for (int mf = 0; mf < 4; ++mf) {
        const int r0 = m0 + wm * 64 + mf * 16 + (lane >> 2);
#pragma unroll
        for (int nf = 0; nf < 8; ++nf) {
            const int c = n0 + wn * 64 + nf * 8 + (lane & 3) * 2;
            float2 bv = *reinterpret_cast<const float2*>(bias + c);
            float o0x = acc[mf][nf][0] + bv.x;
            float o0y = acc[mf][nf][1] + bv.y;
            float o1x = acc[mf][nf][2] + bv.x;
            float o1y = acc[mf][nf][3] + bv.y;
            if (mode == 2) {
                o0x *= oscale; o0y *= oscale; o1x *= oscale; o1y *= oscale;
                *reinterpret_cast<__half2*>(Ch + (size_t)r0 * Dm + c) =
                    __halves2half2(__float2half_rn(o0x), __float2half_rn(o0y));
                *reinterpret_cast<__half2*>(Ch + (size_t)(r0 + 8) * Dm + c) =
                    __halves2half2(__float2half_rn(o1x), __float2half_rn(o1y));
            } else {
                *reinterpret_cast<float2*>(Cf + (size_t)r0 * Dm + c)       = make_float2(o0x, o0y);
                *reinterpret_cast<float2*>(Cf + (size_t)(r0 + 8) * Dm + c) = make_float2(o1x, o1y);
            }
        }
    }
}

constexpr float QSCALE = 0.125f * 1.44269504088896f;

__global__ __launch_bounds__(128)
void k_proj3(const __half* __restrict__ x16, const __half* __restrict__ w16,
             const float* __restrict__ bq, const float* __restrict__ bk,
             const float* __restrict__ bv,
             __half* __restrict__ q, __half* __restrict__ k, __half* __restrict__ v)
{
    const size_t WSZ = (size_t)Dm * Dm;
    const int z = blockIdx.z;
    if (z == 0)      gemm1_core(x16, w16,           bq, nullptr, q, 2, QSCALE);
    else if (z == 1) gemm1_core(x16, w16 + WSZ,     bk, nullptr, k, 2, 1.f);
    else             gemm1_core(x16, w16 + 2 * WSZ, bv, nullptr, v, 2, 1.f);
}

__global__ __launch_bounds__(128)
void k_oproj(const __half* __restrict__ c16, const __half* __restrict__ wo,
             const float* __restrict__ bo, float* __restrict__ out)
{
    gemm1_core(c16, wo, bo, out, nullptr, 0, 1.f);
}

// ---------------------------------------------------------------------------
// Flash attention (round-12 version, f32-accumulate -- at HMMA roofline).
// fp16 QK^T and PV; 4 warps x 32 q-rows; P in registers; K cp.async 2-buf;
// V register-prefetch + byte_perm pack; 1 syncthreads per tile.
// ---------------------------------------------------------------------------
constexpr int ATTN_SMEM = 37376;

__global__ __launch_bounds__(128)
void k_attn(const int* __restrict__ mask, __half* __restrict__ C16)
{
    extern __shared__ __align__(16) unsigned char smraw[];
    unsigned* Vp  = (unsigned*)(smraw + 18432);
    int*      msk = (int*)(smraw + 36864);

    const int tid  = threadIdx.x;
    const int lane = tid & 31;
    const int wq   = tid >> 5;
    const int bh   = blockIdx.y;
    const int b    = bh >> 4;
    const int h    = bh & 15;
    const int q0   = blockIdx.x * 128;

    const uint32_t KstA = (uint32_t)__cvta_generic_to_shared(smraw);
    const uint32_t VpA  = KstA + 18432;
    const uint32_t mskA = KstA + 36864;

    const int krow = tid >> 1;
    const int kcb  = (tid & 1) * 64;
    const uint32_t kDst = (uint32_t)(krow * 144 + kcb);

    const int kpi  = tid >> 2;
    const int dseg = (tid & 3) * 16;

    const int rowB = (lane & 7) + ((lane >> 1) & 8);
    const uint32_t offB = (uint32_t)(rowB * 144 + ((lane >> 3) & 1) * 16);

    unsigned qf[2][4][4];
    {
        const __half* qbase = g_Q16 + ((size_t)(b * Sn + q0 + wq * 32) * Dm + h * Dh);
#pragma unroll
        for (int mt = 0; mt < 2; ++mt)
#pragma unroll
            for (int c = 0; c < 4; ++c)
#pragma unroll
                for (int j = 0; j < 4; ++j) {
                    int row = mt * 16 + (lane >> 2) + ((j & 1) << 3);
                    int col = c * 16 + (lane & 3) * 2 + ((j >> 1) << 3);
                    qf[mt][c][j] = *reinterpret_cast<const unsigned*>(
                        qbase + (size_t)row * Dm + col);
                }
    }

    float of[2][8][4];
#pragma unroll
    for (int mt = 0; mt < 2; ++mt)
#pragma unroll
        for (int nf = 0; nf < 8; ++nf)
#pragma unroll
            for (int j = 0; j < 4; ++j) of[mt][nf][j] = 0.f;

    float mr[2][2] = { {-INFINITY, -INFINITY}, {-INFINITY, -INFINITY} };
    float lr[2][2] = { {0.f, 0.f}, {0.f, 0.f} };

    const int NT = Sn / 64;

    {
        const __half* kp = g_K16 + (size_t)(b * Sn + krow) * Dm + h * Dh + kcb / 2;
#pragma unroll
        for (int i = 0; i < 4; ++i)
            cpasync16(KstA + kDst + i * 16, kp + i * 8);
        if (tid < 16) cpasync16(mskA + tid * 16, mask + (size_t)b * Sn + tid * 4);
        asm volatile("cp.async.commit_group;");
    }
    uint4 va0, va1, vb0, vb1;
    {
        const __half* vsrc = g_V16 + (size_t)(b * Sn + 2 * kpi) * Dm + h * Dh + dseg;
        va0 = *reinterpret_cast<const uint4*>(vsrc);
        va1 = *reinterpret_cast<const uint4*>(vsrc + 8);
        vb0 = *reinterpret_cast<const uint4*>(vsrc + Dm);
        vb1 = *reinterpret_cast<const uint4*>(vsrc + Dm + 8);
    }

    for (int kt = 0; kt < NT; ++kt) {
        const int p = kt & 1;

        {
            unsigned* vrow = Vp + p * 2304 + dseg * 36 + kpi;
            vrow[0 * 36]  = __byte_perm(va0.x, vb0.x, 0x5410);
            vrow[1 * 36]  = __byte_perm(va0.x, vb0.x, 0x7632);
            vrow[2 * 36]  = __byte_perm(va0.y, vb0.y, 0x5410);
            vrow[3 * 36]  = __byte_perm(va0.y, vb0.y, 0x7632);
            vrow[4 * 36]  = __byte_perm(va0.z, vb0.z, 0x5410);
            vrow[5 * 36]  = __byte_perm(va0.z, vb0.z, 0x7632);
            vrow[6 * 36]  = __byte_perm(va0.w, vb0.w, 0x5410);
            vrow[7 * 36]  = __byte_perm(va0.w, vb0.w, 0x7632);
            vrow[8 * 36]  = __byte_perm(va1.x, vb1.x, 0x5410);
            vrow[9 * 36]  = __byte_perm(va1.x, vb1.x, 0x7632);
            vrow[10 * 36] = __byte_perm(va1.y, vb1.y, 0x5410);
            vrow[11 * 36] = __byte_perm(va1.y, vb1.y, 0x7632);
            vrow[12 * 36] = __byte_perm(va1.z, vb1.z, 0x5410);
            vrow[13 * 36] = __byte_perm(va1.z, vb1.z, 0x7632);
            vrow[14 * 36] = __byte_perm(va1.w, vb1.w, 0x5410);
            vrow[15 * 36] = __byte_perm(va1.w, vb1.w, 0x7632);
        }
        if (kt + 1 < NT) {
            const __half* vsrc = g_V16 +
                (size_t)(b * Sn + (kt + 1) * 64 + 2 * kpi) * Dm + h * Dh + dseg;
            va0 = *reinterpret_cast<const uint4*>(vsrc);
            va1 = *reinterpret_cast<const uint4*>(vsrc + 8);
            vb0 = *reinterpret_cast<const uint4*>(vsrc + Dm);
            vb1 = *reinterpret_cast<const uint4*>(vsrc + Dm + 8);
        }

        asm volatile("cp.async.wait_group 0;");
        __syncthreads();

        if (kt + 1 < NT) {
            const __half* kp = g_K16 +
                (size_t)(b * Sn + (kt + 1) * 64 + krow) * Dm + h * Dh + kcb / 2;
            const uint32_t bofs = (uint32_t)((p ^ 1) * 9216);
#pragma unroll
            for (int i = 0; i < 4; ++i)
                cpasync16(KstA + bofs + kDst + i * 16, kp + i * 8);
            if (tid < 16)
                cpasync16(mskA + (p ^ 1) * 256 + tid * 16,
                          mask + (size_t)b * Sn + (kt + 1) * 64 + tid * 4);
            asm volatile("cp.async.commit_group;");
        }

        float sf[2][8][4];
#pragma unroll
        for (int mt = 0; mt < 2; ++mt)
#pragma unroll
            for (int nf = 0; nf < 8; ++nf)
#pragma unroll
                for (int j = 0; j < 4; ++j) sf[mt][nf][j] = 0.f;

        const uint32_t kBase = KstA + (uint32_t)(p * 9216) + offB;
#pragma unroll
        for (int c = 0; c < 4; ++c) {
#pragma unroll
            for (int np = 0; np < 4; ++np) {
                unsigned t[4];
                ldm_x4(t, kBase + (uint32_t)(np * 16 * 144 + c * 32));
                unsigned b0[2] = { t[0], t[1] };
                unsigned b1[2] = { t[2], t[3] };
#pragma unroll
                for (int mt = 0; mt < 2; ++mt) {
                    mma16h(sf[mt][np * 2],     qf[mt][c], b0);
                    mma16h(sf[mt][np * 2 + 1], qf[mt][c], b1);
                }
            }
        }

        const int* mk = msk + p * 64;
#pragma unroll
        for (int mt = 0; mt < 2; ++mt) {
            float tmax0 = -INFINITY, tmax1 = -INFINITY;
#pragma unroll
            for (int nf = 0; nf < 8; ++nf) {
                const int c = nf * 8 + (lane & 3) * 2;
                if (!mk[c])     { sf[mt][nf][0] = -1e20f; sf[mt][nf][2] = -1e20f; }
                if (!mk[c + 1]) { sf[mt][nf][1] = -1e20f; sf[mt][nf][3] = -1e20f; }
                tmax0 = fmaxf(tmax0, fmaxf(sf[mt][nf][0], sf[mt][nf][1]));
                tmax1 = fmaxf(tmax1, fmaxf(sf[mt][nf][2], sf[mt][nf][3]));
            }
            tmax0 = fmaxf(tmax0, __shfl_xor_sync(0xffffffff, tmax0, 1));
            tmax0 = fmaxf(tmax0, __shfl_xor_sync(0xffffffff, tmax0, 2));
            tmax1 = fmaxf(tmax1, __shfl_xor_sync(0xffffffff, tmax1, 1));
            tmax1 = fmaxf(tmax1, __shfl_xor_sync(0xffffffff, tmax1, 2));

            const float mn0 = fmaxf(mr[mt][0], tmax0);
            const float mn1 = fmaxf(mr[mt][1], tmax1);
            const float a0  = ex2(mr[mt][0] - mn0);
            const float a1  = ex2(mr[mt][1] - mn1);
            lr[mt][0] *= a0; lr[mt][1] *= a1;
            if (a0 != 1.f || a1 != 1.f) {
#pragma unroll
                for (int nf = 0; nf < 8; ++nf) {
                    of[mt][nf][0] *= a0; of[mt][nf][1] *= a0;
                    of[mt][nf][2] *= a1; of[mt][nf][3] *= a1;
                }
            }

            float s0 = 0.f, s1 = 0.f;
#pragma unroll
            for (int nf = 0; nf < 8; ++nf) {
                sf[mt][nf][0] = ex2(sf[mt][nf][0] - mn0);
                sf[mt][nf][1] = ex2(sf[mt][nf][1] - mn0);
                sf[mt][nf][2] = ex2(sf[mt][nf][2] - mn1);
                sf[mt][nf][3] = ex2(sf[mt][nf][3] - mn1);
                s0 += sf[mt][nf][0] + sf[mt][nf][1];
                s1 += sf[mt][nf][2] + sf[mt][nf][3];
            }
            s0 += __shfl_xor_sync(0xffffffff, s0, 1);
            s0 += __shfl_xor_sync(0xffffffff, s0, 2);
            s1 += __shfl_xor_sync(0xffffffff, s1, 1);
            s1 += __shfl_xor_sync(0xffffffff, s1, 2);
            lr[mt][0] += s0; lr[mt][1] += s1;
            mr[mt][0] = mn0; mr[mt][1] = mn1;
        }

        const uint32_t vBase = VpA + (uint32_t)(p * 9216) + offB;
#pragma unroll
        for (int c = 0; c < 4; ++c) {
            unsigned af[2][4];
#pragma unroll
            for (int mt = 0; mt < 2; ++mt) {
                af[mt][0] = packh2(sf[mt][2 * c][0],     sf[mt][2 * c][1]);
                af[mt][1] = packh2(sf[mt][2 * c][2],     sf[mt][2 * c][3]);
                af[mt][2] = packh2(sf[mt][2 * c + 1][0], sf[mt][2 * c + 1][1]);
                af[mt][3] = packh2(sf[mt][2 * c + 1][2], sf[mt][2 * c + 1][3]);
            }
#pragma unroll
            for (int np = 0; np < 4; ++np) {
                unsigned t[4];
                ldm_x4(t, vBase + (uint32_t)(np * 16 * 144 + c * 32));
                unsigned b0[2] = { t[0], t[1] };
                unsigned b1[2] = { t[2], t[3] };
#pragma unroll
                for (int mt = 0; mt < 2; ++mt) {
                    mma16h(of[mt][np * 2],     af[mt], b0);
                    mma16h(of[mt][np * 2 + 1], af[mt], b1);
                }
            }
        }
    }

#pragma unroll
    for (int mt = 0; mt < 2; ++mt) {
        const float inv0 = 1.f / lr[mt][0];
        const float inv1 = 1.f / lr[mt][1];
        const size_t rbase = (size_t)(b * Sn + q0 + wq * 32 + mt * 16);
#pragma unroll
        for (int nf = 0; nf < 8; ++nf) {
            const int c = h * Dh + nf * 8 + (lane & 3) * 2;
            const int r = lane >> 2;
            *reinterpret_cast<__half2*>(C16 + (rbase + r) * Dm + c) =
                __halves2half2(__float2half_rn(of[mt][nf][0] * inv0),
                               __float2half_rn(of[mt][nf][1] * inv0));
            *reinterpret_cast<__half2*>(C16 + (rbase + r + 8) * Dm + c) =
                __halves2half2(__float2half_rn(of[mt][nf][2] * inv1),
                               __float2half_rn(of[mt][nf][3] * inv1));
        }
    }
}

// ---------------------------------------------------------------------------
// Launch
// ---------------------------------------------------------------------------
extern "C" void kernel_launch(void* const* d_in, const int* in_sizes, int n_in,
                              void* d_out, int out_size)
{
    const float* query = (const float*)d_in[0];
    const int*   mask  = (const int*)  d_in[1];
    const float* Wq    = (const float*)d_in[2];
    const float* bq    = (const float*)d_in[3];
    const float* Wk    = (const float*)d_in[4];
    const float* bk    = (const float*)d_in[5];
    const float* Wv    = (const float*)d_in[6];
    const float* bv    = (const float*)d_in[7];
    const float* Wo    = (const float*)d_in[8];
    const float* bo    = (const float*)d_in[9];
    float* out = (float*)d_out;

    static int init_done = 0;
    if (!init_done) {
        cudaFuncSetAttribute(k_proj3, cudaFuncAttributeMaxDynamicSharedMemorySize, GEMM_SMEM);
        cudaFuncSetAttribute(k_oproj, cudaFuncAttributeMaxDynamicSharedMemorySize, GEMM_SMEM);
        cudaFuncSetAttribute(k_attn,  cudaFuncAttributeMaxDynamicSharedMemorySize, ATTN_SMEM);
        init_done = 1;
    }

    __half *x16, *c16, *w16, *q16, *k16, *v16;
    cudaGetSymbolAddress((void**)&x16, g_X16);
    cudaGetSymbolAddress((void**)&c16, g_C16);
    cudaGetSymbolAddress((void**)&w16, g_W16);
    cudaGetSymbolAddress((void**)&q16, g_Q16);
    cudaGetSymbolAddress((void**)&k16, g_K16);
    cudaGetSymbolAddress((void**)&v16, g_V16);

    const size_t WSZ = (size_t)Dm * Dm;
    const int nX4 = MTOT * Dm / 4;
    const int nW4 = Dm * Dm / 4;

    // conversions
    k_cvtX<<<(nX4 + 255) / 256, 256>>>(query, x16, nX4);
    dim3 gw((nW4 + 255) / 256, 4);
    k_cvtW<<<gw, 256>>>(Wq, Wk, Wv, Wo, w16, nW4);

    // QKV projections (128x128 tiles, K-stage 64)
    dim3 gq(Dm / 128, MTOT / 128, 3);
    k_proj3<<<gq, 128, GEMM_SMEM>>>(x16, w16, bq, bk, bv, q16, k16, v16);

    // attention (round-12 core)
    dim3 ga(Sn / 128, Bn * Hn);
    k_attn<<<ga, 128, ATTN_SMEM>>>(mask, c16);

    // output projection
    dim3 go(Dm / 128, MTOT / 128);
    k_oproj<<<go, 128, GEMM_SMEM>>>(c16, w16 + 3 * WSZ, bo, out);
}

// round 16
// speedup vs baseline: 1.6264x; 1.6264x over previous
#include <cuda_runtime.h>
#include <cuda_fp16.h>
#include <math.h>
#include <stdint.h>

constexpr int Bn  = 4;
constexpr int Sn  = 2048;
constexpr int Dm  = 1024;
constexpr int Hn  = 16;
constexpr int Dh  = 64;
constexpr int MTOT = Bn * Sn;   // 8192

// fp16 scratch
__device__ __half g_Q16[(size_t)MTOT * Dm];   // pre-scaled by 0.125*log2e
__device__ __half g_K16[(size_t)MTOT * Dm];
__device__ __half g_V16[(size_t)MTOT * Dm];
__device__ __half g_X16[(size_t)MTOT * Dm];
__device__ __half g_C16[(size_t)MTOT * Dm];
__device__ __half g_W16[4][(size_t)Dm * Dm];

// ---------------------------------------------------------------------------
// helpers
// ---------------------------------------------------------------------------
__device__ __forceinline__ float ex2(float x) {
    float y;
    asm("ex2.approx.ftz.f32 %0, %1;" : "=f"(y) : "f"(x));
    return y;
}

__device__ __forceinline__ void mma16h(float* d, const unsigned* a, const unsigned* b) {
    asm volatile(
        "mma.sync.aligned.m16n8k16.row.col.f32.f16.f16.f32 "
        "{%0,%1,%2,%3},{%4,%5,%6,%7},{%8,%9},{%0,%1,%2,%3};"
        : "+f"(d[0]), "+f"(d[1]), "+f"(d[2]), "+f"(d[3])
        : "r"(a[0]), "r"(a[1]), "r"(a[2]), "r"(a[3]), "r"(b[0]), "r"(b[1]));
}

__device__ __forceinline__ void ldm_x4(unsigned* r, uint32_t addr) {
    asm volatile(
        "ldmatrix.sync.aligned.m8n8.x4.shared.b16 {%0,%1,%2,%3}, [%4];"
        : "=r"(r[0]), "=r"(r[1]), "=r"(r[2]), "=r"(r[3]) : "r"(addr));
}

__device__ __forceinline__ unsigned packh2(float a, float b) {
    __half2 h = __floats2half2_rn(a, b);    // low = a
    return *reinterpret_cast<unsigned*>(&h);
}

__device__ __forceinline__ void cpasync16(uint32_t dst, const void* src) {
    asm volatile("cp.async.cg.shared.global [%0], [%1], 16;" :: "r"(dst), "l"(src));
}

// ---------------------------------------------------------------------------
// conversions
// ---------------------------------------------------------------------------
__global__ __launch_bounds__(256)
void k_cvtX(const float* __restrict__ src, __half* __restrict__ dst, int n4)
{
    int i = blockIdx.x * blockDim.x + threadIdx.x;
    if (i >= n4) return;
    float4 v = reinterpret_cast<const float4*>(src)[i];
    reinterpret_cast<__half2*>(dst)[i * 2 + 0] =
        __halves2half2(__float2half_rn(v.x), __float2half_rn(v.y));
    reinterpret_cast<__half2*>(dst)[i * 2 + 1] =
        __halves2half2(__float2half_rn(v.z), __float2half_rn(v.w));
}

__global__ __launch_bounds__(256)
void k_cvtW(const float* __restrict__ wq, const float* __restrict__ wk,
            const float* __restrict__ wv, const float* __restrict__ wo,
            __half* __restrict__ dst, int n4)
{
    int i = blockIdx.x * blockDim.x + threadIdx.x;
    if (i >= n4) return;
    const float* src = (blockIdx.y == 0) ? wq : (blockIdx.y == 1) ? wk
                       : (blockIdx.y == 2) ? wv : wo;
    __half* out = dst + (size_t)blockIdx.y * Dm * Dm;
    float4 v = reinterpret_cast<const float4*>(src)[i];
    reinterpret_cast<__half2*>(out)[i * 2 + 0] =
        __halves2half2(__float2half_rn(v.x), __float2half_rn(v.y));
    reinterpret_cast<__half2*>(out)[i * 2 + 1] =
        __halves2half2(__float2half_rn(v.z), __float2half_rn(v.w));
}

// ---------------------------------------------------------------------------
// Single-pass fp16 GEMM core (round-12 config):
// CTA tile 128x128, 4 warps (2x2) of 64x64, K-stage 32, cp.async double buffer.
// Stage tile: 128 rows x 80 B (64 B data + 16 pad); A and B tiles per buffer.
// mode: 0 = f32 out, 2 = fp16 out (scaled by oscale)
// ---------------------------------------------------------------------------
constexpr int GROWB = 80;
constexpr int GTILE = 128 * GROWB;           // 10240 B per matrix
constexpr int GEMM_SMEM = 2 * 2 * GTILE;     // 40960 B

__device__ __forceinline__ void gemm1_core(
    const __half* __restrict__ A,
    const __half* __restrict__ Bh,
    const float* __restrict__ bias,
    float* __restrict__ Cf, __half* __restrict__ Ch, int mode, float oscale)
{
    extern __shared__ __align__(16) unsigned char gsm[];

    const int tid  = threadIdx.x;
    const int lane = tid & 31;
    const int warp = tid >> 5;           // 0..3
    const int wm   = warp >> 1;          // 0..1
    const int wn   = warp & 1;           // 0..1
    const int m0   = blockIdx.y * 128;
    const int n0   = blockIdx.x * 128;

    const uint32_t smemBase = (uint32_t)__cvta_generic_to_shared(gsm);

    const int frow = tid;
    const uint32_t fDst = (uint32_t)(frow * GROWB);
    const __half* srcA = A  + (size_t)(m0 + frow) * Dm;
    const __half* srcB = Bh + (size_t)(n0 + frow) * Dm;

    const uint32_t aOff = (uint32_t)((lane & 15) * GROWB + ((lane >> 4) & 1) * 16)
                          + wm * 64 * GROWB;
    const uint32_t bOff = (uint32_t)(((lane & 7) + ((lane >> 1) & 8)) * GROWB
                          + ((lane >> 3) & 1) * 16)
                          + wn * 64 * GROWB;

    float acc[4][8][4];
#pragma unroll
    for (int mf = 0; mf < 4; ++mf)
#pragma unroll
        for (int nf = 0; nf < 8; ++nf)
#pragma unroll
            for (int j = 0; j < 4; ++j) acc[mf][nf][j] = 0.f;

    const int NSTAGE = Dm / 32;

    {
#pragma unroll
        for (int i = 0; i < 4; ++i) {
            cpasync16(smemBase + fDst + i * 16,          srcA + i * 8);
            cpasync16(smemBase + GTILE + fDst + i * 16,  srcB + i * 8);
        }
        asm volatile("cp.async.commit_group;");
    }

    int buf = 0;
    for (int st = 0; st < NSTAGE; ++st) {
        asm volatile("cp.async.wait_group 0;");
        __syncthreads();

        if (st + 1 < NSTAGE) {
            const uint32_t nb = (uint32_t)((buf ^ 1) * 2 * GTILE);
#pragma unroll
            for (int i = 0; i < 4; ++i) {
                cpasync16(smemBase + nb + fDst + i * 16,
                          srcA + (st + 1) * 32 + i * 8);
                cpasync16(smemBase + nb + GTILE + fDst + i * 16,
                          srcB + (st + 1) * 32 + i * 8);
            }
            asm volatile("cp.async.commit_group;");
        }

        const uint32_t aB = smemBase + (uint32_t)(buf * 2 * GTILE) + aOff;
        const uint32_t bB = smemBase + (uint32_t)(buf * 2 * GTILE) + GTILE + bOff;

#pragma unroll
        for (int ks = 0; ks < 2; ++ks) {
            const uint32_t kadd = ks * 32;
            unsigned af[4][4], bf[8][2];
#pragma unroll
            for (int mf = 0; mf < 4; ++mf)
                ldm_x4(af[mf], aB + mf * (16 * GROWB) + kadd);
#pragma unroll
            for (int np = 0; np < 4; ++np) {
                unsigned t[4];
                ldm_x4(t, bB + np * (16 * GROWB) + kadd);
                bf[np * 2][0] = t[0]; bf[np * 2][1] = t[1];
                bf[np * 2 + 1][0] = t[2]; bf[np * 2 + 1][1] = t[3];
            }
#pragma unroll
            for (int mf = 0; mf < 4; ++mf)
#pragma unroll
                for (int nf = 0; nf < 8; ++nf)
                    mma16h(acc[mf][nf], af[mf], bf[nf]);
        }
        buf ^= 1;
    }

#pragma unroll
    for (int mf = 0; mf < 4; ++mf) {
        const int r0 = m0 + wm * 64 + mf * 16 + (lane >> 2);
#pragma unroll
        for (int nf = 0; nf < 8; ++nf) {
            const int c = n0 + wn * 64 + nf * 8 + (lane & 3) * 2;
            float2 bv = *reinterpret_cast<const float2*>(bias + c);
            float o0x = acc[mf][nf][0] + bv.x;
            float o0y = acc[mf][nf][1] + bv.y;
            float o1x = acc[mf][nf][2] + bv.x;
            float o1y = acc[mf][nf][3] + bv.y;
            if (mode == 2) {
                o0x *= oscale; o0y *= oscale; o1x *= oscale; o1y *= oscale;
                *reinterpret_cast<__half2*>(Ch + (size_t)r0 * Dm + c) =
                    __halves2half2(__float2half_rn(o0x), __float2half_rn(o0y));
                *reinterpret_cast<__half2*>(Ch + (size_t)(r0 + 8) * Dm + c) =
                    __halves2half2(__float2half_rn(o1x), __float2half_rn(o1y));
            } else {
                *reinterpret_cast<float2*>(Cf + (size_t)r0 * Dm + c)       = make_float2(o0x, o0y);
                *reinterpret_cast<float2*>(Cf + (size_t)(r0 + 8) * Dm + c) = make_float2(o1x, o1y);
            }
        }
    }
}

constexpr float QSCALE = 0.125f * 1.44269504088896f;

__global__ __launch_bounds__(128)
void k_proj3(const __half* __restrict__ x16, const __half* __restrict__ w16,
             const float* __restrict__ bq, const float* __restrict__ bk,
             const float* __restrict__ bv,
             __half* __restrict__ q, __half* __restrict__ k, __half* __restrict__ v)
{
    const size_t WSZ = (size_t)Dm * Dm;
    const int z = blockIdx.z;
    if (z == 0)      gemm1_core(x16, w16,           bq, nullptr, q, 2, QSCALE);
    else if (z == 1) gemm1_core(x16, w16 + WSZ,     bk, nullptr, k, 2, 1.f);
    else             gemm1_core(x16, w16 + 2 * WSZ, bv, nullptr, v, 2, 1.f);
}

__global__ __launch_bounds__(128)
void k_oproj(const __half* __restrict__ c16, const __half* __restrict__ wo,
             const float* __restrict__ bo, float* __restrict__ out)
{
    gemm1_core(c16, wo, bo, out, nullptr, 0, 1.f);
}

// ---------------------------------------------------------------------------
// Flash attention (round-12 version, f32-accumulate -- at HMMA roofline).
// fp16 QK^T and PV; 4 warps x 32 q-rows; P in registers; K cp.async 2-buf;
// V register-prefetch + byte_perm pack; 1 syncthreads per tile.
// ---------------------------------------------------------------------------
constexpr int ATTN_SMEM = 37376;

__global__ __launch_bounds__(128)
void k_attn(const int* __restrict__ mask, __half* __restrict__ C16)
{
    extern __shared__ __align__(16) unsigned char smraw[];
    unsigned* Vp  = (unsigned*)(smraw + 18432);
    int*      msk = (int*)(smraw + 36864);

    const int tid  = threadIdx.x;
    const int lane = tid & 31;
    const int wq   = tid >> 5;
    const int bh   = blockIdx.y;
    const int b    = bh >> 4;
    const int h    = bh & 15;
    const int q0   = blockIdx.x * 128;

    const uint32_t KstA = (uint32_t)__cvta_generic_to_shared(smraw);
    const uint32_t VpA  = KstA + 18432;
    const uint32_t mskA = KstA + 36864;

    const int krow = tid >> 1;
    const int kcb  = (tid & 1) * 64;
    const uint32_t kDst = (uint32_t)(krow * 144 + kcb);

    const int kpi  = tid >> 2;
    const int dseg = (tid & 3) * 16;

    const int rowB = (lane & 7) + ((lane >> 1) & 8);
    const uint32_t offB = (uint32_t)(rowB * 144 + ((lane >> 3) & 1) * 16);

    unsigned qf[2][4][4];
    {
        const __half* qbase = g_Q16 + ((size_t)(b * Sn + q0 + wq * 32) * Dm + h * Dh);
#pragma unroll
        for (int mt = 0; mt < 2; ++mt)
#pragma unroll
            for (int c = 0; c < 4; ++c)
#pragma unroll
                for (int j = 0; j < 4; ++j) {
                    int row = mt * 16 + (lane >> 2) + ((j & 1) << 3);
                    int col = c * 16 + (lane & 3) * 2 + ((j >> 1) << 3);
                    qf[mt][c][j] = *reinterpret_cast<const unsigned*>(
                        qbase + (size_t)row * Dm + col);
                }
    }

    float of[2][8][4];
#pragma unroll
    for (int mt = 0; mt < 2; ++mt)
#pragma unroll
        for (int nf = 0; nf < 8; ++nf)
#pragma unroll
            for (int j = 0; j < 4; ++j) of[mt][nf][j] = 0.f;

    float mr[2][2] = { {-INFINITY, -INFINITY}, {-INFINITY, -INFINITY} };
    float lr[2][2] = { {0.f, 0.f}, {0.f, 0.f} };

    const int NT = Sn / 64;

    {
        const __half* kp = g_K16 + (size_t)(b * Sn + krow) * Dm + h * Dh + kcb / 2;
#pragma unroll
        for (int i = 0; i < 4; ++i)
            cpasync16(KstA + kDst + i * 16, kp + i * 8);
        if (tid < 16) cpasync16(mskA + tid * 16, mask + (size_t)b * Sn + tid * 4);
        asm volatile("cp.async.commit_group;");
    }
    uint4 va0, va1, vb0, vb1;
    {
        const __half* vsrc = g_V16 + (size_t)(b * Sn + 2 * kpi) * Dm + h * Dh + dseg;
        va0 = *reinterpret_cast<const uint4*>(vsrc);
        va1 = *reinterpret_cast<const uint4*>(vsrc + 8);
        vb0 = *reinterpret_cast<const uint4*>(vsrc + Dm);
        vb1 = *reinterpret_cast<const uint4*>(vsrc + Dm + 8);
    }

    for (int kt = 0; kt < NT; ++kt) {
        const int p = kt & 1;

        {
            unsigned* vrow = Vp + p * 2304 + dseg * 36 + kpi;
            vrow[0 * 36]  = __byte_perm(va0.x, vb0.x, 0x5410);
            vrow[1 * 36]  = __byte_perm(va0.x, vb0.x, 0x7632);
            vrow[2 * 36]  = __byte_perm(va0.y, vb0.y, 0x5410);
            vrow[3 * 36]  = __byte_perm(va0.y, vb0.y, 0x7632);
            vrow[4 * 36]  = __byte_perm(va0.z, vb0.z, 0x5410);
            vrow[5 * 36]  = __byte_perm(va0.z, vb0.z, 0x7632);
            vrow[6 * 36]  = __byte_perm(va0.w, vb0.w, 0x5410);
            vrow[7 * 36]  = __byte_perm(va0.w, vb0.w, 0x7632);
            vrow[8 * 36]  = __byte_perm(va1.x, vb1.x, 0x5410);
            vrow[9 * 36]  = __byte_perm(va1.x, vb1.x, 0x7632);
            vrow[10 * 36] = __byte_perm(va1.y, vb1.y, 0x5410);
            vrow[11 * 36] = __byte_perm(va1.y, vb1.y, 0x7632);
            vrow[12 * 36] = __byte_perm(va1.z, vb1.z, 0x5410);
            vrow[13 * 36] = __byte_perm(va1.z, vb1.z, 0x7632);
            vrow[14 * 36] = __byte_perm(va1.w, vb1.w, 0x5410);
            vrow[15 * 36] = __byte_perm(va1.w, vb1.w, 0x7632);
        }
        if (kt + 1 < NT) {
            const __half* vsrc = g_V16 +
                (size_t)(b * Sn + (kt + 1) * 64 + 2 * kpi) * Dm + h * Dh + dseg;
            va0 = *reinterpret_cast<const uint4*>(vsrc);
            va1 = *reinterpret_cast<const uint4*>(vsrc + 8);
            vb0 = *reinterpret_cast<const uint4*>(vsrc + Dm);
            vb1 = *reinterpret_cast<const uint4*>(vsrc + Dm + 8);
        }

        asm volatile("cp.async.wait_group 0;");
        __syncthreads();

        if (kt + 1 < NT) {
            const __half* kp = g_K16 +
                (size_t)(b * Sn + (kt + 1) * 64 + krow) * Dm + h * Dh + kcb / 2;
            const uint32_t bofs = (uint32_t)((p ^ 1) * 9216);
#pragma unroll
            for (int i = 0; i < 4; ++i)
                cpasync16(KstA + bofs + kDst + i * 16, kp + i * 8);
            if (tid < 16)
                cpasync16(mskA + (p ^ 1) * 256 + tid * 16,
                          mask + (size_t)b * Sn + (kt + 1) * 64 + tid * 4);
            asm volatile("cp.async.commit_group;");
        }

        float sf[2][8][4];
#pragma unroll
        for (int mt = 0; mt < 2; ++mt)
#pragma unroll
            for (int nf = 0; nf < 8; ++nf)
#pragma unroll
                for (int j = 0; j < 4; ++j) sf[mt][nf][j] = 0.f;

        const uint32_t kBase = KstA + (uint32_t)(p * 9216) + offB;
#pragma unroll
        for (int c = 0; c < 4; ++c) {
#pragma unroll
            for (int np = 0; np < 4; ++np) {
                unsigned t[4];
                ldm_x4(t, kBase + (uint32_t)(np * 16 * 144 + c * 32));
                unsigned b0[2] = { t[0], t[1] };
                unsigned b1[2] = { t[2], t[3] };
#pragma unroll
                for (int mt = 0; mt < 2; ++mt) {
                    mma16h(sf[mt][np * 2],     qf[mt][c], b0);
                    mma16h(sf[mt][np * 2 + 1], qf[mt][c], b1);
                }
            }
        }

        const int* mk = msk + p * 64;
#pragma unroll
        for (int mt = 0; mt < 2; ++mt) {
            float tmax0 = -INFINITY, tmax1 = -INFINITY;
#pragma unroll
            for (int nf = 0; nf < 8; ++nf) {
                const int c = nf * 8 + (lane & 3) * 2;
                if (!mk[c])     { sf[mt][nf][0] = -1e20f; sf[mt][nf][2] = -1e20f; }
                if (!mk[c + 1]) { sf[mt][nf][1] = -1e20f; sf[mt][nf][3] = -1e20f; }
                tmax0 = fmaxf(tmax0, fmaxf(sf[mt][nf][0], sf[mt][nf][1]));
                tmax1 = fmaxf(tmax1, fmaxf(sf[mt][nf][2], sf[mt][nf][3]));
            }
            tmax0 = fmaxf(tmax0, __shfl_xor_sync(0xffffffff, tmax0, 1));
            tmax0 = fmaxf(tmax0, __shfl_xor_sync(0xffffffff, tmax0, 2));
            tmax1 = fmaxf(tmax1, __shfl_xor_sync(0xffffffff, tmax1, 1));
            tmax1 = fmaxf(tmax1, __shfl_xor_sync(0xffffffff, tmax1, 2));

            const float mn0 = fmaxf(mr[mt][0], tmax0);
            const float mn1 = fmaxf(mr[mt][1], tmax1);
            const float a0  = ex2(mr[mt][0] - mn0);
            const float a1  = ex2(mr[mt][1] - mn1);
            lr[mt][0] *= a0; lr[mt][1] *= a1;
            if (a0 != 1.f || a1 != 1.f) {
#pragma unroll
                for (int nf = 0; nf < 8; ++nf) {
                    of[mt][nf][0] *= a0; of[mt][nf][1] *= a0;
                    of[mt][nf][2] *= a1; of[mt][nf][3] *= a1;
                }
            }

            float s0 = 0.f, s1 = 0.f;
#pragma unroll
            for (int nf = 0; nf < 8; ++nf) {
                sf[mt][nf][0] = ex2(sf[mt][nf][0] - mn0);
                sf[mt][nf][1] = ex2(sf[mt][nf][1] - mn0);
                sf[mt][nf][2] = ex2(sf[mt][nf][2] - mn1);
                sf[mt][nf][3] = ex2(sf[mt][nf][3] - mn1);
                s0 += sf[mt][nf][0] + sf[mt][nf][1];
                s1 += sf[mt][nf][2] + sf[mt][nf][3];
            }
            s0 += __shfl_xor_sync(0xffffffff, s0, 1);
            s0 += __shfl_xor_sync(0xffffffff, s0, 2);
            s1 += __shfl_xor_sync(0xffffffff, s1, 1);
            s1 += __shfl_xor_sync(0xffffffff, s1, 2);
            lr[mt][0] += s0; lr[mt][1] += s1;
            mr[mt][0] = mn0; mr[mt][1] = mn1;
        }

        const uint32_t vBase = VpA + (uint32_t)(p * 9216) + offB;
#pragma unroll
        for (int c = 0; c < 4; ++c) {
            unsigned af[2][4];
#pragma unroll
            for (int mt = 0; mt < 2; ++mt) {
                af[mt][0] = packh2(sf[mt][2 * c][0],     sf[mt][2 * c][1]);
                af[mt][1] = packh2(sf[mt][2 * c][2],     sf[mt][2 * c][3]);
                af[mt][2] = packh2(sf[mt][2 * c + 1][0], sf[mt][2 * c + 1][1]);
                af[mt][3] = packh2(sf[mt][2 * c + 1][2], sf[mt][2 * c + 1][3]);
            }
#pragma unroll
            for (int np = 0; np < 4; ++np) {
                unsigned t[4];
                ldm_x4(t, vBase + (uint32_t)(np * 16 * 144 + c * 32));
                unsigned b0[2] = { t[0], t[1] };
                unsigned b1[2] = { t[2], t[3] };
#pragma unroll
                for (int mt = 0; mt < 2; ++mt) {
                    mma16h(of[mt][np * 2],     af[mt], b0);
                    mma16h(of[mt][np * 2 + 1], af[mt], b1);
                }
            }
        }
    }

#pragma unroll
    for (int mt = 0; mt < 2; ++mt) {
        const float inv0 = 1.f / lr[mt][0];
        const float inv1 = 1.f / lr[mt][1];
        const size_t rbase = (size_t)(b * Sn + q0 + wq * 32 + mt * 16);
#pragma unroll
        for (int nf = 0; nf < 8; ++nf) {
            const int c = h * Dh + nf * 8 + (lane & 3) * 2;
            const int r = lane >> 2;
            *reinterpret_cast<__half2*>(C16 + (rbase + r) * Dm + c) =
                __halves2half2(__float2half_rn(of[mt][nf][0] * inv0),
                               __float2half_rn(of[mt][nf][1] * inv0));
            *reinterpret_cast<__half2*>(C16 + (rbase + r + 8) * Dm + c) =
                __halves2half2(__float2half_rn(of[mt][nf][2] * inv1),
                               __float2half_rn(of[mt][nf][3] * inv1));
        }
    }
}

// ---------------------------------------------------------------------------
// Launch
// ---------------------------------------------------------------------------
extern "C" void kernel_launch(void* const* d_in, const int* in_sizes, int n_in,
                              void* d_out, int out_size)
{
    const float* query = (const float*)d_in[0];
    const int*   mask  = (const int*)  d_in[1];
    const float* Wq    = (const float*)d_in[2];
    const float* bq    = (const float*)d_in[3];
    const float* Wk    = (const float*)d_in[4];
    const float* bk    = (const float*)d_in[5];
    const float* Wv    = (const float*)d_in[6];
    const float* bv    = (const float*)d_in[7];
    const float* Wo    = (const float*)d_in[8];
    const float* bo    = (const float*)d_in[9];
    float* out = (float*)d_out;

    static int init_done = 0;
    if (!init_done) {
        cudaFuncSetAttribute(k_proj3, cudaFuncAttributeMaxDynamicSharedMemorySize, GEMM_SMEM);
        cudaFuncSetAttribute(k_oproj, cudaFuncAttributeMaxDynamicSharedMemorySize, GEMM_SMEM);
        cudaFuncSetAttribute(k_attn,  cudaFuncAttributeMaxDynamicSharedMemorySize, ATTN_SMEM);
        init_done = 1;
    }

    __half *x16, *c16, *w16, *q16, *k16, *v16;
    cudaGetSymbolAddress((void**)&x16, g_X16);
    cudaGetSymbolAddress((void**)&c16, g_C16);
    cudaGetSymbolAddress((void**)&w16, g_W16);
    cudaGetSymbolAddress((void**)&q16, g_Q16);
    cudaGetSymbolAddress((void**)&k16, g_K16);
    cudaGetSymbolAddress((void**)&v16, g_V16);

    const size_t WSZ = (size_t)Dm * Dm;
    const int nX4 = MTOT * Dm / 4;
    const int nW4 = Dm * Dm / 4;

    // conversions
    k_cvtX<<<(nX4 + 255) / 256, 256>>>(query, x16, nX4);
    dim3 gw((nW4 + 255) / 256, 4);
    k_cvtW<<<gw, 256>>>(Wq, Wk, Wv, Wo, w16, nW4);

    // QKV projections (128x128 tiles, round-12 config)
    dim3 gq(Dm / 128, MTOT / 128, 3);
    k_proj3<<<gq, 128, GEMM_SMEM>>>(x16, w16, bq, bk, bv, q16, k16, v16);

    // attention
    dim3 ga(Sn / 128, Bn * Hn);
    k_attn<<<ga, 128, ATTN_SMEM>>>(mask, c16);

    // output projection
    dim3 go(Dm / 128, MTOT / 128);
    k_oproj<<<go, 128, GEMM_SMEM>>>(c16, w16 + 3 * WSZ, bo, out);
}